// round 5
// baseline (speedup 1.0000x reference)
#include <cuda_runtime.h>
#include <cuda_bf16.h>
#include <math.h>
#include <stdint.h>

#define D 64
#define NNODES 512
#define NTOT 4096
#define HDIM 192
#define EMAX 131072
#define NWARP 16
#define THREADS (NWARP * 32)
#define ROWB 144

// ---- smem layout (bytes) ----
#define OFF_WHI 0                       // [192][72] bf16 rows (144B) = 27648
#define OFF_WLO 27648
#define OFF_W2  55296                   // 192 f32 permuted = 768
#define OFF_A   56064                   // 16 warps x (hi 4608 + lo 4608)
#define AWARP   9216
#define OFF_SS  203520                  // 16w x 32 int
#define OFF_SD  205568
#define OFF_AT  207616
#define SMEM_TOTAL 209664

__device__ float g_denom[NTOT];
__device__ float g_Pd[NTOT * HDIM];   // pair-permuted: [n][g*16 + 2r + j] = P[n][g*16+r+8j]
__device__ float g_Ps[NTOT * HDIM];
__device__ int   g_is64;

__device__ __forceinline__ long long ldidx(const void* ei, int i, int is64) {
    return is64 ? ((const long long*)ei)[i] : (long long)((const int*)ei)[i];
}
__device__ __forceinline__ void ldsm4(uint32_t* r, uint32_t a) {
    asm volatile("ldmatrix.sync.aligned.m8n8.x4.shared.b16 {%0,%1,%2,%3}, [%4];"
                 : "=r"(r[0]), "=r"(r[1]), "=r"(r[2]), "=r"(r[3]) : "r"(a));
}
__device__ __forceinline__ void mma_bf16(float* c, const uint32_t* a, const uint32_t* b) {
    asm volatile("mma.sync.aligned.m16n8k16.row.col.f32.bf16.bf16.f32 "
                 "{%0,%1,%2,%3}, {%4,%5,%6,%7}, {%8,%9}, {%0,%1,%2,%3};"
                 : "+f"(c[0]), "+f"(c[1]), "+f"(c[2]), "+f"(c[3])
                 : "r"(a[0]), "r"(a[1]), "r"(a[2]), "r"(a[3]), "r"(b[0]), "r"(b[1]));
}
__device__ __forceinline__ void red4(float* p, float a, float b, float c, float d) {
    asm volatile("red.global.add.v4.f32 [%0], {%1,%2,%3,%4};"
                 :: "l"(p), "f"(a), "f"(b), "f"(c), "f"(d) : "memory");
}
__device__ __forceinline__ uint2 pack_hi_lo(float4 v, uint2* lo) {
    __nv_bfloat16 h0 = __float2bfloat16(v.x), h1 = __float2bfloat16(v.y);
    __nv_bfloat16 h2 = __float2bfloat16(v.z), h3 = __float2bfloat16(v.w);
    __nv_bfloat16 l0 = __float2bfloat16(v.x - __bfloat162float(h0));
    __nv_bfloat16 l1 = __float2bfloat16(v.y - __bfloat162float(h1));
    __nv_bfloat16 l2 = __float2bfloat16(v.z - __bfloat162float(h2));
    __nv_bfloat16 l3 = __float2bfloat16(v.w - __bfloat162float(h3));
    uint2 hi, lv;
    hi.x = (uint32_t)__bfloat16_as_ushort(h0) | ((uint32_t)__bfloat16_as_ushort(h1) << 16);
    hi.y = (uint32_t)__bfloat16_as_ushort(h2) | ((uint32_t)__bfloat16_as_ushort(h3) << 16);
    lv.x = (uint32_t)__bfloat16_as_ushort(l0) | ((uint32_t)__bfloat16_as_ushort(l1) << 16);
    lv.y = (uint32_t)__bfloat16_as_ushort(l2) | ((uint32_t)__bfloat16_as_ushort(l3) << 16);
    *lo = lv;
    return hi;
}
__device__ __forceinline__ float gelu_x(float x) {
    return 0.5f * x * (1.0f + erff(x * 0.70710678118654752f));
}
// m -> pair-permuted storage index
__device__ __forceinline__ int perm_m(int m) {
    return (m & ~15) | ((m & 7) << 1) | ((m >> 3) & 1);
}

// zero + int64/int32 detection (block 0)
__global__ void zero_kernel(float* __restrict__ out, const void* __restrict__ ei) {
    int i = blockIdx.x * blockDim.x + threadIdx.x;
    if (i < NTOT * D) out[i] = 0.0f;
    if (i < NTOT)     g_denom[i] = 0.0f;
    if (blockIdx.x == 0) {
        const long long* p = (const long long*)ei;
        long long v = p[threadIdx.x];
        int ok = (v >= 0 && v < NTOT);
        int all = __syncthreads_and(ok);
        if (threadIdx.x == 0) g_is64 = all;
    }
}

// P[n][o] = sum_k nf[n][k] * W1[o][64*half + k], stored pair-permuted.
__global__ __launch_bounds__(256, 2) void precompute_kernel(
    const float* __restrict__ nf, const float* __restrict__ W1)
{
    extern __shared__ float psm[];
    float* Ws = psm;                // [64][192]: Ws[k*192+o]
    float* Ns = psm + 64 * HDIM;    // [64][64]

    int half = blockIdx.x & 1;
    int tile = blockIdx.x >> 1;
    int tid = threadIdx.x, lane = tid & 31, warp = tid >> 5;
    float* P = half ? g_Ps : g_Pd;

    for (int i = tid; i < HDIM * 64; i += 256) {
        int o = i >> 6, k = i & 63;
        Ws[k * HDIM + o] = W1[o * HDIM + 64 * half + k];
    }
    for (int i = tid; i < 64 * 64 / 4; i += 256)
        ((float4*)Ns)[i] = ((const float4*)(nf + tile * 64 * D))[i];
    __syncthreads();

    float acc[8][6];
    #pragma unroll
    for (int e = 0; e < 8; ++e)
        #pragma unroll
        for (int j = 0; j < 6; ++j) acc[e][j] = 0.0f;

    const float* hb = Ns + (warp * 8) * 64;
    #pragma unroll 4
    for (int k = 0; k < 64; ++k) {
        const float* w = Ws + k * HDIM + lane;
        float wv[6];
        #pragma unroll
        for (int j = 0; j < 6; ++j) wv[j] = w[32 * j];
        #pragma unroll
        for (int e = 0; e < 8; ++e) {
            float hv = hb[e * 64 + k];
            #pragma unroll
            for (int j = 0; j < 6; ++j) acc[e][j] = fmaf(hv, wv[j], acc[e][j]);
        }
    }
    int nbase = tile * 64 + warp * 8;
    #pragma unroll
    for (int e = 0; e < 8; ++e)
        #pragma unroll
        for (int j = 0; j < 6; ++j) {
            int o = lane + 32 * j;
            P[(nbase + e) * HDIM + perm_m(o)] = acc[e][j];
        }
}

// Warp-autonomous: 32-edge warp tiles. W = MMA A operand (m=192), edges = B
// operand hoisted in registers. Acc initialized with Pd[dst]+Ps[src] via
// pair-permuted LDG.64. gelu*W2 epilogue, shuffle reduce, exp/mask, atomics.
__global__ __launch_bounds__(THREADS, 1) void score_kernel(
    const float* __restrict__ adj, const float* __restrict__ W1,
    const float* __restrict__ W2, const void* __restrict__ ei,
    float* __restrict__ out, int E, int nwt)
{
    extern __shared__ __align__(16) char sm[];
    uint32_t smb = (uint32_t)__cvta_generic_to_shared(sm);
    float* W2p = (float*)(sm + OFF_W2);

    int tid = threadIdx.x, lane = tid & 31, wid = tid >> 5;
    int is64 = g_is64;

    // Stage W1c (cols 128..191) split hi/lo (rows = output o, K-major, 144B rows)
    for (int i = tid; i < HDIM * 16; i += THREADS) {
        int o = i >> 4, r = i & 15;
        float4 v = *(const float4*)(W1 + o * HDIM + 128 + r * 4);
        uint2 lo, hi = pack_hi_lo(v, &lo);
        *(uint2*)(sm + OFF_WHI + o * ROWB + r * 8) = hi;
        *(uint2*)(sm + OFF_WLO + o * ROWB + r * 8) = lo;
    }
    for (int i = tid; i < HDIM; i += THREADS) W2p[perm_m(i)] = W2[i];
    __syncthreads();

    char* Ahi = sm + OFF_A + wid * AWARP;
    char* Alo = Ahi + 4608;
    uint32_t ahi_u = smb + OFF_A + wid * AWARP;
    uint32_t whi_u = smb + OFF_WHI;
    int*   sSw = (int*)(sm + OFF_SS) + wid * 32;
    int*   sDw = (int*)(sm + OFF_SD) + wid * 32;
    float* ATw = (float*)(sm + OFF_AT) + wid * 32;

    int gw = blockIdx.x * NWARP + wid;
    for (int wt = gw; wt < nwt; wt += gridDim.x * NWARP) {
        int tbase = wt * 32;
        // ---- indices: one edge per lane ----
        int ge = tbase + lane;
        long long sL = 0, dL = 0;
        if (ge < E) {
            sL = ldidx(ei, ge, is64);
            dL = ldidx(ei, E + ge, is64);
        }
        sSw[lane] = (int)sL; sDw[lane] = (int)dL;
        // ---- gather + split own row (stagger j to avoid STS conflicts) ----
        {
            const float4* rowp =
                (const float4*)(adj + (sL * NNODES + ((int)dL & (NNODES - 1))) * D);
            #pragma unroll
            for (int j = 0; j < 16; ++j) {
                int jl = (j + ((lane >> 3) << 2)) & 15;
                float4 v = (ge < E) ? rowp[jl] : make_float4(0.f, 0.f, 0.f, 0.f);
                uint2 lo, hi = pack_hi_lo(v, &lo);
                *(uint2*)(Ahi + lane * ROWB + jl * 8) = hi;
                *(uint2*)(Alo + lane * ROWB + jl * 8) = lo;
            }
        }
        __syncwarp();

        // ---- hoist B fragments (edges), hi+lo ----
        uint32_t bh[4][4][2], bl[4][4][2];
        #pragma unroll
        for (int np = 0; np < 2; ++np)
            #pragma unroll
            for (int kk = 0; kk < 4; ++kk) {
                uint32_t ad = ahi_u + (uint32_t)((np * 16 + (lane & 7) + ((lane >> 4) << 3)) * ROWB
                                                 + kk * 32 + ((lane >> 3) & 1) * 16);
                uint32_t r[4];
                ldsm4(r, ad);
                bh[np*2][kk][0] = r[0]; bh[np*2][kk][1] = r[1];
                bh[np*2+1][kk][0] = r[2]; bh[np*2+1][kk][1] = r[3];
                ldsm4(r, ad + 4608);
                bl[np*2][kk][0] = r[0]; bl[np*2][kk][1] = r[1];
                bl[np*2+1][kk][0] = r[2]; bl[np*2+1][kk][1] = r[3];
            }

        // ---- per-thread edge-column byte offsets into P ----
        uint32_t doff[4][2], soff[4][2];
        #pragma unroll
        for (int nn = 0; nn < 4; ++nn)
            #pragma unroll
            for (int c = 0; c < 2; ++c) {
                int e = nn * 8 + 2 * (lane & 3) + c;
                doff[nn][c] = (uint32_t)sDw[e] * (HDIM * 4);
                soff[nn][c] = (uint32_t)sSw[e] * (HDIM * 4);
            }
        uint32_t roff = (uint32_t)((lane >> 2) << 3);

        float z[4][2] = {{0.f,0.f},{0.f,0.f},{0.f,0.f},{0.f,0.f}};
        const char* pdB = (const char*)g_Pd;
        const char* psB = (const char*)g_Ps;

        #pragma unroll
        for (int mc = 0; mc < 12; ++mc) {
            float acc[4][4];
            // init with Pd[dst]+Ps[src] (pair-permuted: float2 = rows m, m+8)
            #pragma unroll
            for (int nn = 0; nn < 4; ++nn)
                #pragma unroll
                for (int c = 0; c < 2; ++c) {
                    float2 a = *(const float2*)(pdB + doff[nn][c] + mc * 64 + roff);
                    float2 b = *(const float2*)(psB + soff[nn][c] + mc * 64 + roff);
                    acc[nn][c]     = a.x + b.x;
                    acc[nn][c + 2] = a.y + b.y;
                }
            #pragma unroll
            for (int kk = 0; kk < 4; ++kk) {
                uint32_t wa = whi_u + (uint32_t)((mc * 16 + (lane & 15)) * ROWB
                                                 + kk * 32 + (lane >> 4) * 16);
                uint32_t ah[4], al[4];
                ldsm4(ah, wa);
                ldsm4(al, wa + 27648);
                #pragma unroll
                for (int nn = 0; nn < 4; ++nn) {
                    mma_bf16(acc[nn], ah, bh[nn][kk]);
                    mma_bf16(acc[nn], ah, bl[nn][kk]);
                    mma_bf16(acc[nn], al, bh[nn][kk]);
                }
            }
            // epilogue partial: z += gelu(y)*W2 for rows m, m+8
            float2 w2v = *(const float2*)((const char*)W2p + mc * 64 + roff);
            #pragma unroll
            for (int nn = 0; nn < 4; ++nn) {
                z[nn][0] = fmaf(gelu_x(acc[nn][0]), w2v.x, z[nn][0]);
                z[nn][0] = fmaf(gelu_x(acc[nn][2]), w2v.y, z[nn][0]);
                z[nn][1] = fmaf(gelu_x(acc[nn][1]), w2v.x, z[nn][1]);
                z[nn][1] = fmaf(gelu_x(acc[nn][3]), w2v.y, z[nn][1]);
            }
        }

        // reduce over m across lanes (bits 2,3,4 of lane)
        float zf[4][2];
        #pragma unroll
        for (int nn = 0; nn < 4; ++nn)
            #pragma unroll
            for (int c = 0; c < 2; ++c) {
                float v = z[nn][c];
                v += __shfl_xor_sync(0xffffffffu, v, 4);
                v += __shfl_xor_sync(0xffffffffu, v, 8);
                v += __shfl_xor_sync(0xffffffffu, v, 16);
                zf[nn][c] = v;
            }
        // each lane owns exactly one edge
        float za0 = (lane & 4) ? zf[0][1] : zf[0][0];
        float za1 = (lane & 4) ? zf[1][1] : zf[1][0];
        float za2 = (lane & 4) ? zf[2][1] : zf[2][0];
        float za3 = (lane & 4) ? zf[3][1] : zf[3][0];
        float zb0 = (lane & 8) ? za1 : za0;
        float zb1 = (lane & 8) ? za3 : za2;
        float zown = (lane & 16) ? zb1 : zb0;
        int e_o = ((lane >> 3) << 3) + 2 * (lane & 3) + ((lane >> 2) & 1);
        {
            int s = sSw[e_o], d = sDw[e_o];
            int df = s > d ? s - d : d - s;
            float attn = (tbase + e_o < E && df > 1) ? expf(zown) : 0.0f;
            ATw[e_o] = attn;
            if (attn != 0.0f) atomicAdd(&g_denom[d], attn);
        }
        __syncwarp();

        // weighted accumulate: 2 edges per pass, 4 cols/lane, red.v4
        #pragma unroll
        for (int ep = 0; ep < 16; ++ep) {
            int e = 2 * ep + (lane >> 4);
            float a = ATw[e];
            if (a != 0.0f) {
                int c4 = lane & 15;
                uint2 h = *(const uint2*)(Ahi + e * ROWB + c4 * 8);
                uint2 l = *(const uint2*)(Alo + e * ROWB + c4 * 8);
                float f0 = __uint_as_float((h.x & 0xffffu) << 16) + __uint_as_float((l.x & 0xffffu) << 16);
                float f1 = __uint_as_float(h.x & 0xffff0000u)     + __uint_as_float(l.x & 0xffff0000u);
                float f2 = __uint_as_float((h.y & 0xffffu) << 16) + __uint_as_float((l.y & 0xffffu) << 16);
                float f3 = __uint_as_float(h.y & 0xffff0000u)     + __uint_as_float(l.y & 0xffff0000u);
                red4(out + sDw[e] * D + c4 * 4, f0 * a, f1 * a, f2 * a, f3 * a);
            }
        }
        __syncwarp();
    }
}

__global__ void finalize_kernel(float* __restrict__ out) {
    int i = blockIdx.x * blockDim.x + threadIdx.x;
    if (i < NTOT * D) {
        float dn = g_denom[i >> 6];
        out[i] = out[i] / (dn == 0.0f ? 1.0f : dn);
    }
}

extern "C" void kernel_launch(void* const* d_in, const int* in_sizes, int n_in,
                              void* d_out, int out_size) {
    const float* nf  = (const float*)d_in[0];
    const float* adj = (const float*)d_in[1];
    const float* W1  = (const float*)d_in[2];
    const float* W2  = (const float*)d_in[3];
    const void*  ei  = d_in[4];
    int E = in_sizes[4] / 2;
    if (E > EMAX) E = EMAX;

    const int pre_smem = (64 * HDIM + 64 * 64) * sizeof(float);
    cudaFuncSetAttribute(precompute_kernel, cudaFuncAttributeMaxDynamicSharedMemorySize, pre_smem);
    cudaFuncSetAttribute(score_kernel, cudaFuncAttributeMaxDynamicSharedMemorySize, SMEM_TOTAL);

    zero_kernel<<<(NTOT * D + 255) / 256, 256>>>((float*)d_out, ei);
    precompute_kernel<<<(NTOT / 64) * 2, 256, pre_smem>>>(nf, W1);

    int nwt = (E + 31) / 32;
    int grid = (nwt + NWARP - 1) / NWARP;
    if (grid > 148) grid = 148;
    score_kernel<<<grid, THREADS, SMEM_TOTAL>>>(adj, W1, W2, ei, (float*)d_out, E, nwt);

    finalize_kernel<<<(NTOT * D + 255) / 256, 256>>>((float*)d_out);
}

// round 6
// speedup vs baseline: 1.5346x; 1.5346x over previous
#include <cuda_runtime.h>
#include <cuda_bf16.h>
#include <math.h>
#include <stdint.h>

#define D 64
#define NNODES 512
#define NTOT 4096
#define HDIM 192
#define EMAX 131072
#define NWARP 16
#define THREADS (NWARP * 32)
#define ROWB 144

// ---- smem layout (bytes) ----
#define OFF_WHI 0                       // [192][72] bf16 rows (144B) = 27648
#define OFF_WLO 27648
#define OFF_W2  55296                   // 192 f32 permuted = 768
#define OFF_A   56064                   // 16 warps x (hi 4608 + lo 4608)
#define AWARP   9216
#define OFF_SS  203520                  // 16w x 32 int
#define OFF_SD  205568
#define OFF_AT  207616
#define SMEM_TOTAL 209664

__device__ float g_denom[NTOT];
__device__ float g_Pd[NTOT * HDIM];   // pair-permuted: [n][g*16 + 2r + j] = P[n][g*16+r+8j]
__device__ float g_Ps[NTOT * HDIM];
__device__ int   g_is64;

__device__ __forceinline__ long long ldidx(const void* ei, int i, int is64) {
    return is64 ? ((const long long*)ei)[i] : (long long)((const int*)ei)[i];
}
__device__ __forceinline__ void ldsm4(uint32_t* r, uint32_t a) {
    asm volatile("ldmatrix.sync.aligned.m8n8.x4.shared.b16 {%0,%1,%2,%3}, [%4];"
                 : "=r"(r[0]), "=r"(r[1]), "=r"(r[2]), "=r"(r[3]) : "r"(a));
}
__device__ __forceinline__ void mma_bf16(float* c, const uint32_t* a, const uint32_t* b) {
    asm volatile("mma.sync.aligned.m16n8k16.row.col.f32.bf16.bf16.f32 "
                 "{%0,%1,%2,%3}, {%4,%5,%6,%7}, {%8,%9}, {%0,%1,%2,%3};"
                 : "+f"(c[0]), "+f"(c[1]), "+f"(c[2]), "+f"(c[3])
                 : "r"(a[0]), "r"(a[1]), "r"(a[2]), "r"(a[3]), "r"(b[0]), "r"(b[1]));
}
__device__ __forceinline__ void red4(float* p, float a, float b, float c, float d) {
    asm volatile("red.global.add.v4.f32 [%0], {%1,%2,%3,%4};"
                 :: "l"(p), "f"(a), "f"(b), "f"(c), "f"(d) : "memory");
}
__device__ __forceinline__ uint2 pack_hi_lo(float4 v, uint2* lo) {
    __nv_bfloat16 h0 = __float2bfloat16(v.x), h1 = __float2bfloat16(v.y);
    __nv_bfloat16 h2 = __float2bfloat16(v.z), h3 = __float2bfloat16(v.w);
    __nv_bfloat16 l0 = __float2bfloat16(v.x - __bfloat162float(h0));
    __nv_bfloat16 l1 = __float2bfloat16(v.y - __bfloat162float(h1));
    __nv_bfloat16 l2 = __float2bfloat16(v.z - __bfloat162float(h2));
    __nv_bfloat16 l3 = __float2bfloat16(v.w - __bfloat162float(h3));
    uint2 hi, lv;
    hi.x = (uint32_t)__bfloat16_as_ushort(h0) | ((uint32_t)__bfloat16_as_ushort(h1) << 16);
    hi.y = (uint32_t)__bfloat16_as_ushort(h2) | ((uint32_t)__bfloat16_as_ushort(h3) << 16);
    lv.x = (uint32_t)__bfloat16_as_ushort(l0) | ((uint32_t)__bfloat16_as_ushort(l1) << 16);
    lv.y = (uint32_t)__bfloat16_as_ushort(l2) | ((uint32_t)__bfloat16_as_ushort(l3) << 16);
    *lo = lv;
    return hi;
}
__device__ __forceinline__ float gelu_x(float x) {
    return 0.5f * x * (1.0f + erff(x * 0.70710678118654752f));
}
// m -> pair-permuted storage index
__device__ __forceinline__ int perm_m(int m) {
    return (m & ~15) | ((m & 7) << 1) | ((m >> 3) & 1);
}

// zero + int64/int32 detection (block 0)
__global__ void zero_kernel(float* __restrict__ out, const void* __restrict__ ei) {
    int i = blockIdx.x * blockDim.x + threadIdx.x;
    if (i < NTOT * D) out[i] = 0.0f;
    if (i < NTOT)     g_denom[i] = 0.0f;
    if (blockIdx.x == 0) {
        const long long* p = (const long long*)ei;
        long long v = p[threadIdx.x];
        int ok = (v >= 0 && v < NTOT);
        int all = __syncthreads_and(ok);
        if (threadIdx.x == 0) g_is64 = all;
    }
}

// P[n][o] = sum_k nf[n][k] * W1[o][64*half + k], stored pair-permuted.
__global__ __launch_bounds__(256, 2) void precompute_kernel(
    const float* __restrict__ nf, const float* __restrict__ W1)
{
    extern __shared__ float psm[];
    float* Ws = psm;                // [64][192]: Ws[k*192+o]
    float* Ns = psm + 64 * HDIM;    // [64][64]

    int half = blockIdx.x & 1;
    int tile = blockIdx.x >> 1;
    int tid = threadIdx.x, lane = tid & 31, warp = tid >> 5;
    float* P = half ? g_Ps : g_Pd;

    for (int i = tid; i < HDIM * 64; i += 256) {
        int o = i >> 6, k = i & 63;
        Ws[k * HDIM + o] = W1[o * HDIM + 64 * half + k];
    }
    for (int i = tid; i < 64 * 64 / 4; i += 256)
        ((float4*)Ns)[i] = ((const float4*)(nf + tile * 64 * D))[i];
    __syncthreads();

    float acc[8][6];
    #pragma unroll
    for (int e = 0; e < 8; ++e)
        #pragma unroll
        for (int j = 0; j < 6; ++j) acc[e][j] = 0.0f;

    const float* hb = Ns + (warp * 8) * 64;
    #pragma unroll 4
    for (int k = 0; k < 64; ++k) {
        const float* w = Ws + k * HDIM + lane;
        float wv[6];
        #pragma unroll
        for (int j = 0; j < 6; ++j) wv[j] = w[32 * j];
        #pragma unroll
        for (int e = 0; e < 8; ++e) {
            float hv = hb[e * 64 + k];
            #pragma unroll
            for (int j = 0; j < 6; ++j) acc[e][j] = fmaf(hv, wv[j], acc[e][j]);
        }
    }
    int nbase = tile * 64 + warp * 8;
    #pragma unroll
    for (int e = 0; e < 8; ++e)
        #pragma unroll
        for (int j = 0; j < 6; ++j) {
            int o = lane + 32 * j;
            P[(nbase + e) * HDIM + perm_m(o)] = acc[e][j];
        }
}

// Warp-autonomous: 32-edge warp tiles. W = MMA A operand (m=192), edges = B
// operand hoisted in registers. Acc initialized with Pd[dst]+Ps[src] via
// pair-permuted LDG.64. gelu*W2 epilogue, shuffle reduce, exp/mask, atomics.
__global__ __launch_bounds__(THREADS, 1) void score_kernel(
    const float* __restrict__ adj, const float* __restrict__ W1,
    const float* __restrict__ W2, const void* __restrict__ ei,
    float* __restrict__ out, int E, int nwt)
{
    extern __shared__ __align__(16) char sm[];
    uint32_t smb = (uint32_t)__cvta_generic_to_shared(sm);
    float* W2p = (float*)(sm + OFF_W2);

    int tid = threadIdx.x, lane = tid & 31, wid = tid >> 5;
    int is64 = g_is64;

    // Stage W1c (cols 128..191) split hi/lo (rows = output o, K-major, 144B rows)
    for (int i = tid; i < HDIM * 16; i += THREADS) {
        int o = i >> 4, r = i & 15;
        float4 v = *(const float4*)(W1 + o * HDIM + 128 + r * 4);
        uint2 lo, hi = pack_hi_lo(v, &lo);
        *(uint2*)(sm + OFF_WHI + o * ROWB + r * 8) = hi;
        *(uint2*)(sm + OFF_WLO + o * ROWB + r * 8) = lo;
    }
    for (int i = tid; i < HDIM; i += THREADS) W2p[perm_m(i)] = W2[i];
    __syncthreads();

    char* Ahi = sm + OFF_A + wid * AWARP;
    char* Alo = Ahi + 4608;
    uint32_t ahi_u = smb + OFF_A + wid * AWARP;
    uint32_t whi_u = smb + OFF_WHI;
    int*   sSw = (int*)(sm + OFF_SS) + wid * 32;
    int*   sDw = (int*)(sm + OFF_SD) + wid * 32;
    float* ATw = (float*)(sm + OFF_AT) + wid * 32;

    int gw = blockIdx.x * NWARP + wid;
    for (int wt = gw; wt < nwt; wt += gridDim.x * NWARP) {
        int tbase = wt * 32;
        // ---- indices: one edge per lane ----
        int ge = tbase + lane;
        long long sL = 0, dL = 0;
        if (ge < E) {
            sL = ldidx(ei, ge, is64);
            dL = ldidx(ei, E + ge, is64);
        }
        sSw[lane] = (int)sL; sDw[lane] = (int)dL;
        // ---- gather + split own row (stagger j to avoid STS conflicts) ----
        {
            const float4* rowp =
                (const float4*)(adj + (sL * NNODES + ((int)dL & (NNODES - 1))) * D);
            #pragma unroll
            for (int j = 0; j < 16; ++j) {
                int jl = (j + ((lane >> 3) << 2)) & 15;
                float4 v = (ge < E) ? rowp[jl] : make_float4(0.f, 0.f, 0.f, 0.f);
                uint2 lo, hi = pack_hi_lo(v, &lo);
                *(uint2*)(Ahi + lane * ROWB + jl * 8) = hi;
                *(uint2*)(Alo + lane * ROWB + jl * 8) = lo;
            }
        }
        __syncwarp();

        // ---- hoist B fragments (edges), hi+lo ----
        uint32_t bh[4][4][2], bl[4][4][2];
        #pragma unroll
        for (int np = 0; np < 2; ++np)
            #pragma unroll
            for (int kk = 0; kk < 4; ++kk) {
                uint32_t ad = ahi_u + (uint32_t)((np * 16 + (lane & 7) + ((lane >> 4) << 3)) * ROWB
                                                 + kk * 32 + ((lane >> 3) & 1) * 16);
                uint32_t r[4];
                ldsm4(r, ad);
                bh[np*2][kk][0] = r[0]; bh[np*2][kk][1] = r[1];
                bh[np*2+1][kk][0] = r[2]; bh[np*2+1][kk][1] = r[3];
                ldsm4(r, ad + 4608);
                bl[np*2][kk][0] = r[0]; bl[np*2][kk][1] = r[1];
                bl[np*2+1][kk][0] = r[2]; bl[np*2+1][kk][1] = r[3];
            }

        // ---- per-thread edge-column byte offsets into P ----
        uint32_t doff[4][2], soff[4][2];
        #pragma unroll
        for (int nn = 0; nn < 4; ++nn)
            #pragma unroll
            for (int c = 0; c < 2; ++c) {
                int e = nn * 8 + 2 * (lane & 3) + c;
                doff[nn][c] = (uint32_t)sDw[e] * (HDIM * 4);
                soff[nn][c] = (uint32_t)sSw[e] * (HDIM * 4);
            }
        uint32_t roff = (uint32_t)((lane >> 2) << 3);

        float z[4][2] = {{0.f,0.f},{0.f,0.f},{0.f,0.f},{0.f,0.f}};
        const char* pdB = (const char*)g_Pd;
        const char* psB = (const char*)g_Ps;

        #pragma unroll
        for (int mc = 0; mc < 12; ++mc) {
            float acc[4][4];
            // init with Pd[dst]+Ps[src] (pair-permuted: float2 = rows m, m+8)
            #pragma unroll
            for (int nn = 0; nn < 4; ++nn)
                #pragma unroll
                for (int c = 0; c < 2; ++c) {
                    float2 a = *(const float2*)(pdB + doff[nn][c] + mc * 64 + roff);
                    float2 b = *(const float2*)(psB + soff[nn][c] + mc * 64 + roff);
                    acc[nn][c]     = a.x + b.x;
                    acc[nn][c + 2] = a.y + b.y;
                }
            #pragma unroll
            for (int kk = 0; kk < 4; ++kk) {
                uint32_t wa = whi_u + (uint32_t)((mc * 16 + (lane & 15)) * ROWB
                                                 + kk * 32 + (lane >> 4) * 16);
                uint32_t ah[4], al[4];
                ldsm4(ah, wa);
                ldsm4(al, wa + 27648);
                #pragma unroll
                for (int nn = 0; nn < 4; ++nn) {
                    mma_bf16(acc[nn], ah, bh[nn][kk]);
                    mma_bf16(acc[nn], ah, bl[nn][kk]);
                    mma_bf16(acc[nn], al, bh[nn][kk]);
                }
            }
            // epilogue partial: z += gelu(y)*W2 for rows m, m+8
            float2 w2v = *(const float2*)((const char*)W2p + mc * 64 + roff);
            #pragma unroll
            for (int nn = 0; nn < 4; ++nn) {
                z[nn][0] = fmaf(gelu_x(acc[nn][0]), w2v.x, z[nn][0]);
                z[nn][0] = fmaf(gelu_x(acc[nn][2]), w2v.y, z[nn][0]);
                z[nn][1] = fmaf(gelu_x(acc[nn][1]), w2v.x, z[nn][1]);
                z[nn][1] = fmaf(gelu_x(acc[nn][3]), w2v.y, z[nn][1]);
            }
        }

        // reduce over m across lanes (bits 2,3,4 of lane)
        float zf[4][2];
        #pragma unroll
        for (int nn = 0; nn < 4; ++nn)
            #pragma unroll
            for (int c = 0; c < 2; ++c) {
                float v = z[nn][c];
                v += __shfl_xor_sync(0xffffffffu, v, 4);
                v += __shfl_xor_sync(0xffffffffu, v, 8);
                v += __shfl_xor_sync(0xffffffffu, v, 16);
                zf[nn][c] = v;
            }
        // each lane owns exactly one edge
        float za0 = (lane & 4) ? zf[0][1] : zf[0][0];
        float za1 = (lane & 4) ? zf[1][1] : zf[1][0];
        float za2 = (lane & 4) ? zf[2][1] : zf[2][0];
        float za3 = (lane & 4) ? zf[3][1] : zf[3][0];
        float zb0 = (lane & 8) ? za1 : za0;
        float zb1 = (lane & 8) ? za3 : za2;
        float zown = (lane & 16) ? zb1 : zb0;
        int e_o = ((lane >> 3) << 3) + 2 * (lane & 3) + ((lane >> 2) & 1);
        {
            int s = sSw[e_o], d = sDw[e_o];
            int df = s > d ? s - d : d - s;
            float attn = (tbase + e_o < E && df > 1) ? expf(zown) : 0.0f;
            ATw[e_o] = attn;
            if (attn != 0.0f) atomicAdd(&g_denom[d], attn);
        }
        __syncwarp();

        // weighted accumulate: 2 edges per pass, 4 cols/lane, red.v4
        #pragma unroll
        for (int ep = 0; ep < 16; ++ep) {
            int e = 2 * ep + (lane >> 4);
            float a = ATw[e];
            if (a != 0.0f) {
                int c4 = lane & 15;
                uint2 h = *(const uint2*)(Ahi + e * ROWB + c4 * 8);
                uint2 l = *(const uint2*)(Alo + e * ROWB + c4 * 8);
                float f0 = __uint_as_float((h.x & 0xffffu) << 16) + __uint_as_float((l.x & 0xffffu) << 16);
                float f1 = __uint_as_float(h.x & 0xffff0000u)     + __uint_as_float(l.x & 0xffff0000u);
                float f2 = __uint_as_float((h.y & 0xffffu) << 16) + __uint_as_float((l.y & 0xffffu) << 16);
                float f3 = __uint_as_float(h.y & 0xffff0000u)     + __uint_as_float(l.y & 0xffff0000u);
                red4(out + sDw[e] * D + c4 * 4, f0 * a, f1 * a, f2 * a, f3 * a);
            }
        }
        __syncwarp();
    }
}

__global__ void finalize_kernel(float* __restrict__ out) {
    int i = blockIdx.x * blockDim.x + threadIdx.x;
    if (i < NTOT * D) {
        float dn = g_denom[i >> 6];
        out[i] = out[i] / (dn == 0.0f ? 1.0f : dn);
    }
}

extern "C" void kernel_launch(void* const* d_in, const int* in_sizes, int n_in,
                              void* d_out, int out_size) {
    const float* nf  = (const float*)d_in[0];
    const float* adj = (const float*)d_in[1];
    const float* W1  = (const float*)d_in[2];
    const float* W2  = (const float*)d_in[3];
    const void*  ei  = d_in[4];
    int E = in_sizes[4] / 2;
    if (E > EMAX) E = EMAX;

    const int pre_smem = (64 * HDIM + 64 * 64) * sizeof(float);
    cudaFuncSetAttribute(precompute_kernel, cudaFuncAttributeMaxDynamicSharedMemorySize, pre_smem);
    cudaFuncSetAttribute(score_kernel, cudaFuncAttributeMaxDynamicSharedMemorySize, SMEM_TOTAL);

    zero_kernel<<<(NTOT * D + 255) / 256, 256>>>((float*)d_out, ei);
    precompute_kernel<<<(NTOT / 64) * 2, 256, pre_smem>>>(nf, W1);

    int nwt = (E + 31) / 32;
    int grid = (nwt + NWARP - 1) / NWARP;
    if (grid > 148) grid = 148;
    score_kernel<<<grid, THREADS, SMEM_TOTAL>>>(adj, W1, W2, ei, (float*)d_out, E, nwt);

    finalize_kernel<<<(NTOT * D + 255) / 256, 256>>>((float*)d_out);
}